// round 3
// baseline (speedup 1.0000x reference)
#include <cuda_runtime.h>

// Chunked gated delta rule, fp32.
// Grid: (NSPLIT=4, H=16, B=2) = 128 blocks; each block owns one (b,h) scan for a
// 32-wide Dv slice. 256 threads. State [128][32] lives in shared for all 64 chunks.

#define B_ 2
#define S_ 4096
#define H_ 16
#define DK_ 128
#define DV_ 128
#define CH_ 64
#define NCH (S_ / CH_)
#define NSPLIT 4
#define DVS (DV_ / NSPLIT)      /* 32 */
#define KP (DK_ + 1)            /* 129: padded row stride for Q/K/W */

#define SM_FLOATS (DK_*DVS + 3*CH_*KP + CH_*DVS + CH_*CH_ + 3*CH_)

// solution matrix accessor for the 160-column triangular solve (32 U cols + 128 W cols)
#define XSOL(r,c) (((c) < DVS) ? sU[(r)*DVS + (c)] : sW[(r)*KP + ((c) - DVS)])

__global__ __launch_bounds__(256, 1)
void gdr_kernel(const float* __restrict__ gq, const float* __restrict__ gk,
                const float* __restrict__ gv, const float* __restrict__ gg,
                const float* __restrict__ gb, float* __restrict__ gout)
{
    extern __shared__ float sm[];
    float* sState = sm;                    // [128][32]  running state (Dk x Dv-slice)
    float* sQ     = sState + DK_*DVS;      // [64][129]  l2norm(q) * Dk^-0.5
    float* sK     = sQ + CH_*KP;           // [64][129]  l2norm(k)
    float* sW     = sK + CH_*KP;           // [64][129]  k*beta*exp(gcs) -> kcd (solved)
    float* sU     = sW + CH_*KP;           // [64][32]   v*beta -> u -> v_new
    float* sA     = sU + CH_*DVS;          // [64][64]   A (strict lower) -> attn
    float* sg_    = sA + CH_*CH_;          // [64] cumulative log-decay (gcs)
    float* sbeta  = sg_ + CH_;             // [64]
    float* sdec   = sbeta + CH_;           // [64] exp(gL - gcs)

    const int vs = blockIdx.x, h = blockIdx.y, b = blockIdx.z;
    const int tid  = threadIdx.x;
    const int lane = tid & 31, warp = tid >> 5;

    for (int i = tid; i < DK_*DVS; i += 256) sState[i] = 0.f;

    const float qscale = 0.08838834764831845f; // 128^-0.5

    for (int n = 0; n < NCH; ++n) {
        const int s0 = n * CH_;

        // ---- phase 1: load raw g, beta for this chunk ----
        if (tid < CH_) {
            int idx = (b*S_ + s0 + tid)*H_ + h;
            sg_[tid]   = gg[idx];
            sbeta[tid] = gb[idx];
        }
        __syncthreads();

        // ---- phase 2: warp0 scans g -> gcs; all warps load+normalize Q,K; load V*beta ----
        if (warp == 0) {
            float a0 = sg_[lane], a1 = sg_[lane + 32];
            #pragma unroll
            for (int off = 1; off < 32; off <<= 1) {
                float t = __shfl_up_sync(0xffffffffu, a0, off);
                if (lane >= off) a0 += t;
            }
            #pragma unroll
            for (int off = 1; off < 32; off <<= 1) {
                float t = __shfl_up_sync(0xffffffffu, a1, off);
                if (lane >= off) a1 += t;
            }
            a1 += __shfl_sync(0xffffffffu, a0, 31);
            sg_[lane] = a0; sg_[lane + 32] = a1;
        }
        #pragma unroll
        for (int r8 = 0; r8 < 8; ++r8) {
            int row = warp*8 + r8;
            const float* qp = gq + ((size_t)((b*S_ + s0 + row)*H_ + h))*DK_;
            const float* kp = gk + ((size_t)((b*S_ + s0 + row)*H_ + h))*DK_;
            float q0=qp[lane], q1=qp[lane+32], q2=qp[lane+64], q3=qp[lane+96];
            float k0=kp[lane], k1=kp[lane+32], k2=kp[lane+64], k3=kp[lane+96];
            float sq = q0*q0 + q1*q1 + q2*q2 + q3*q3;
            float sk = k0*k0 + k1*k1 + k2*k2 + k3*k3;
            #pragma unroll
            for (int off = 16; off; off >>= 1) {
                sq += __shfl_xor_sync(0xffffffffu, sq, off);
                sk += __shfl_xor_sync(0xffffffffu, sk, off);
            }
            float rq = rsqrtf(sq + 1e-6f) * qscale;
            float rk = rsqrtf(sk + 1e-6f);
            float* Qr = sQ + row*KP; float* Kr = sK + row*KP;
            Qr[lane]=q0*rq; Qr[lane+32]=q1*rq; Qr[lane+64]=q2*rq; Qr[lane+96]=q3*rq;
            Kr[lane]=k0*rk; Kr[lane+32]=k1*rk; Kr[lane+64]=k2*rk; Kr[lane+96]=k3*rk;
        }
        for (int idx = tid; idx < CH_*DVS; idx += 256) {
            int row = idx >> 5, j = idx & 31;
            sU[idx] = gv[((size_t)((b*S_ + s0 + row)*H_ + h))*DV_ + vs*DVS + j] * sbeta[row];
        }
        __syncthreads();

        const float gL = sg_[CH_ - 1];

        // ---- phase 3: A = strict_lower((k*beta) k^T * decay), W = k*beta*exp(gcs), sdec ----
        if (tid < CH_) sdec[tid] = expf(gL - sg_[tid]);
        {
            const int ty = tid >> 4, tx = tid & 15;
            const int i0 = ty*4, j0 = tx*4;
            float acc[4][4];
            #pragma unroll
            for (int ii = 0; ii < 4; ++ii)
                #pragma unroll
                for (int jj = 0; jj < 4; ++jj) acc[ii][jj] = 0.f;
            for (int d = 0; d < DK_; ++d) {
                float a0=sK[(i0+0)*KP+d], a1=sK[(i0+1)*KP+d],
                      a2=sK[(i0+2)*KP+d], a3=sK[(i0+3)*KP+d];
                float b0=sK[(j0+0)*KP+d], b1=sK[(j0+1)*KP+d],
                      b2=sK[(j0+2)*KP+d], b3=sK[(j0+3)*KP+d];
                acc[0][0]+=a0*b0; acc[0][1]+=a0*b1; acc[0][2]+=a0*b2; acc[0][3]+=a0*b3;
                acc[1][0]+=a1*b0; acc[1][1]+=a1*b1; acc[1][2]+=a1*b2; acc[1][3]+=a1*b3;
                acc[2][0]+=a2*b0; acc[2][1]+=a2*b1; acc[2][2]+=a2*b2; acc[2][3]+=a2*b3;
                acc[3][0]+=a3*b0; acc[3][1]+=a3*b1; acc[3][2]+=a3*b2; acc[3][3]+=a3*b3;
            }
            #pragma unroll
            for (int ii = 0; ii < 4; ++ii) {
                int i = i0 + ii; float bi = sbeta[i], gi = sg_[i];
                #pragma unroll
                for (int jj = 0; jj < 4; ++jj) {
                    int j = j0 + jj;
                    sA[i*64 + j] = (i > j) ? acc[ii][jj] * bi * expf(gi - sg_[j]) : 0.f;
                }
            }
        }
        for (int idx = tid; idx < CH_*DK_; idx += 256) {
            int row = idx >> 7, d = idx & 127;
            sW[row*KP + d] = sK[row*KP + d] * sbeta[row] * expf(sg_[row]);
        }
        __syncthreads();

        // ---- phase 4: blocked forward substitution (I + A) X = [vb | kb*exp(gcs)] ----
        // Solves in place: sU -> u, sW -> kcd. 8-row blocks.
        if (tid < DVS + DK_) {
            #pragma unroll
            for (int i = 1; i < 8; ++i) {
                float acc = 0.f;
                #pragma unroll
                for (int l = 0; l < i; ++l) acc += sA[i*64 + l] * XSOL(l, tid);
                XSOL(i, tid) -= acc;
            }
        }
        __syncthreads();
        for (int blk = 1; blk < 8; ++blk) {
            const int R0 = blk*8, L = R0;
            for (int idx = tid; idx < 8*(DVS + DK_); idx += 256) {
                int r = idx / (DVS + DK_), c = idx % (DVS + DK_);
                int row = R0 + r;
                float acc = 0.f;
                for (int l = 0; l < L; ++l) acc += sA[row*64 + l] * XSOL(l, c);
                XSOL(row, c) -= acc;
            }
            __syncthreads();
            if (tid < DVS + DK_) {
                #pragma unroll
                for (int i = 1; i < 8; ++i) {
                    int row = R0 + i;
                    float acc = 0.f;
                    #pragma unroll
                    for (int l = 0; l < i; ++l) acc += sA[row*64 + R0 + l] * XSOL(R0 + l, tid);
                    XSOL(row, tid) -= acc;
                }
            }
            __syncthreads();
        }

        // ---- phase 5: attn (reuse sA) + v_new = u - kcd @ state (reuse sU) ----
        {
            const int ty = tid >> 4, tx = tid & 15;
            const int i0 = ty*4, j0 = tx*4;
            float acc[4][4];
            #pragma unroll
            for (int ii = 0; ii < 4; ++ii)
                #pragma unroll
                for (int jj = 0; jj < 4; ++jj) acc[ii][jj] = 0.f;
            for (int d = 0; d < DK_; ++d) {
                float a0=sQ[(i0+0)*KP+d], a1=sQ[(i0+1)*KP+d],
                      a2=sQ[(i0+2)*KP+d], a3=sQ[(i0+3)*KP+d];
                float b0=sK[(j0+0)*KP+d], b1=sK[(j0+1)*KP+d],
                      b2=sK[(j0+2)*KP+d], b3=sK[(j0+3)*KP+d];
                acc[0][0]+=a0*b0; acc[0][1]+=a0*b1; acc[0][2]+=a0*b2; acc[0][3]+=a0*b3;
                acc[1][0]+=a1*b0; acc[1][1]+=a1*b1; acc[1][2]+=a1*b2; acc[1][3]+=a1*b3;
                acc[2][0]+=a2*b0; acc[2][1]+=a2*b1; acc[2][2]+=a2*b2; acc[2][3]+=a2*b3;
                acc[3][0]+=a3*b0; acc[3][1]+=a3*b1; acc[3][2]+=a3*b2; acc[3][3]+=a3*b3;
            }
            #pragma unroll
            for (int ii = 0; ii < 4; ++ii) {
                int i = i0 + ii; float gi = sg_[i];
                #pragma unroll
                for (int jj = 0; jj < 4; ++jj) {
                    int j = j0 + jj;
                    sA[i*64 + j] = (i >= j) ? acc[ii][jj] * expf(gi - sg_[j]) : 0.f;
                }
            }
        }
        {
            const int j = tid & 31, r0 = (tid >> 5) * 8;
            float vn[8];
            #pragma unroll
            for (int r = 0; r < 8; ++r) vn[r] = sU[(r0+r)*DVS + j];
            for (int d = 0; d < DK_; ++d) {
                float s = sState[d*DVS + j];
                #pragma unroll
                for (int r = 0; r < 8; ++r) vn[r] -= sW[(r0+r)*KP + d] * s;
            }
            #pragma unroll
            for (int r = 0; r < 8; ++r) sU[(r0+r)*DVS + j] = vn[r];  // each (row,j) owned by one thread
        }
        __syncthreads();

        // ---- phase 6: o = (q*exp(gcs)) @ state + attn @ v_new -> global ----
        {
            const int j = tid & 31, r0 = (tid >> 5) * 8;
            float o1[8], o2[8];
            #pragma unroll
            for (int r = 0; r < 8; ++r) { o1[r] = 0.f; o2[r] = 0.f; }
            for (int d = 0; d < DK_; ++d) {
                float s = sState[d*DVS + j];
                #pragma unroll
                for (int r = 0; r < 8; ++r) o1[r] += sQ[(r0+r)*KP + d] * s;
            }
            for (int d2 = 0; d2 < CH_; ++d2) {
                float u = sU[d2*DVS + j];
                #pragma unroll
                for (int r = 0; r < 8; ++r) o2[r] += sA[(r0+r)*64 + d2] * u;
            }
            #pragma unroll
            for (int r = 0; r < 8; ++r) {
                int row = r0 + r;
                gout[((size_t)((b*S_ + s0 + row)*H_ + h))*DV_ + vs*DVS + j]
                    = o1[r] * expf(sg_[row]) + o2[r];
            }
        }
        __syncthreads();

        // ---- phase 7: state = state*exp(gL) + (k*exp(gL-gcs))^T @ v_new ----
        {
            const int j = tid & 31, d0 = (tid >> 5) * 16;
            const float eL = expf(gL);
            float acc[16];
            #pragma unroll
            for (int dd = 0; dd < 16; ++dd) acc[dd] = 0.f;
            for (int r = 0; r < CH_; ++r) {
                float fv = sdec[r] * sU[r*DVS + j];
                #pragma unroll
                for (int dd = 0; dd < 16; ++dd) acc[dd] += sK[r*KP + d0 + dd] * fv;
            }
            #pragma unroll
            for (int dd = 0; dd < 16; ++dd) {
                int d = d0 + dd;
                sState[d*DVS + j] = sState[d*DVS + j] * eL + acc[dd];
            }
        }
        __syncthreads();
    }
}

extern "C" void kernel_launch(void* const* d_in, const int* in_sizes, int n_in,
                              void* d_out, int out_size) {
    (void)in_sizes; (void)n_in; (void)out_size;
    const float* q    = (const float*)d_in[0];
    const float* k    = (const float*)d_in[1];
    const float* v    = (const float*)d_in[2];
    const float* g    = (const float*)d_in[3];
    const float* beta = (const float*)d_in[4];
    float* out = (float*)d_out;

    size_t smem = (size_t)SM_FLOATS * sizeof(float);  // ~140.8 KB
    cudaFuncSetAttribute(gdr_kernel, cudaFuncAttributeMaxDynamicSharedMemorySize, (int)smem);

    dim3 grid(NSPLIT, H_, B_);
    gdr_kernel<<<grid, 256, smem>>>(q, k, v, g, beta, out);
}

// round 4
// speedup vs baseline: 1.0562x; 1.0562x over previous
#include <cuda_runtime.h>

// Chunked gated delta rule, fp32, round 3.
// Grid (4,16,2)=128 blocks, 512 threads. Each block: one (b,h) scan over a
// 32-wide Dv slice. float4 + transposed-K smem layout, conflict-free pitches.

#define B_ 2
#define S_ 4096
#define H_ 16
#define DK_ 128
#define DV_ 128
#define CH_ 64
#define NCH (S_ / CH_)
#define NSPLIT 4
#define DVS 32            /* Dv slice */
#define KP 132            /* pitch for sQ/sK/sW rows (mod 32 banks = 4) */
#define TP 68             /* pitch for sKt rows (j-contiguous) */
#define AP 68             /* pitch for sA rows */
#define NTHR 512

#define SM_FLOATS (DK_*DVS + 3*CH_*KP + DK_*TP + CH_*DVS + CH_*AP + 3*CH_)

__device__ __forceinline__ float4 ldX4(const float* sU, const float* sW, int r, int c0) {
    if (c0 < DVS) return *(const float4*)&sU[r*DVS + c0];
    return *(const float4*)&sW[r*KP + (c0 - DVS)];
}
__device__ __forceinline__ void stX4(float* sU, float* sW, int r, int c0, float4 v) {
    if (c0 < DVS) *(float4*)&sU[r*DVS + c0] = v;
    else          *(float4*)&sW[r*KP + (c0 - DVS)] = v;
}

__global__ __launch_bounds__(NTHR, 1)
void gdr_kernel(const float* __restrict__ gq, const float* __restrict__ gk,
                const float* __restrict__ gv, const float* __restrict__ gg,
                const float* __restrict__ gb, float* __restrict__ gout)
{
    extern __shared__ float sm[];
    float* sState = sm;                    // [128][32]
    float* sQ     = sState + DK_*DVS;      // [64][132]
    float* sK     = sQ + CH_*KP;           // [64][132]
    float* sW     = sK + CH_*KP;           // [64][132]  kb*exp(gcs) -> kcd
    float* sKt    = sW + CH_*KP;           // [128][68]  K transposed (j contiguous)
    float* sU     = sKt + DK_*TP;          // [64][32]   vb -> u -> v_new
    float* sA     = sU + CH_*DVS;          // [64][68]   A -> attn
    float* sg_    = sA + CH_*AP;           // [64]
    float* sbeta  = sg_ + CH_;             // [64]
    float* sdec   = sbeta + CH_;           // [64]

    const int vs = blockIdx.x, h = blockIdx.y, b = blockIdx.z;
    const int tid = threadIdx.x, lane = tid & 31, warp = tid >> 5;

    for (int i = tid; i < DK_*DVS; i += NTHR) sState[i] = 0.f;
    const float qscale = 0.08838834764831845f; // 128^-0.5

    for (int n = 0; n < NCH; ++n) {
        const int s0 = n * CH_;

        // ---- P1: raw g, beta ----
        if (tid < CH_) {
            int idx = (b*S_ + s0 + tid)*H_ + h;
            sg_[tid]   = gg[idx];
            sbeta[tid] = gb[idx];
        }
        __syncthreads();

        // ---- P2: warp0 inclusive-scans g; all warps load+normalize Q,K; V*beta ----
        if (warp == 0) {
            float a0 = sg_[lane], a1 = sg_[lane + 32];
            #pragma unroll
            for (int off = 1; off < 32; off <<= 1) {
                float t = __shfl_up_sync(0xffffffffu, a0, off);
                if (lane >= off) a0 += t;
            }
            #pragma unroll
            for (int off = 1; off < 32; off <<= 1) {
                float t = __shfl_up_sync(0xffffffffu, a1, off);
                if (lane >= off) a1 += t;
            }
            a1 += __shfl_sync(0xffffffffu, a0, 31);
            sg_[lane] = a0; sg_[lane + 32] = a1;
        }
        #pragma unroll
        for (int r4 = 0; r4 < 4; ++r4) {
            int row = warp*4 + r4;
            const float* qp = gq + ((size_t)((b*S_ + s0 + row)*H_ + h))*DK_;
            const float* kp = gk + ((size_t)((b*S_ + s0 + row)*H_ + h))*DK_;
            float4 q4 = *(const float4*)(qp + lane*4);
            float4 k4 = *(const float4*)(kp + lane*4);
            float sq = q4.x*q4.x + q4.y*q4.y + q4.z*q4.z + q4.w*q4.w;
            float sk = k4.x*k4.x + k4.y*k4.y + k4.z*k4.z + k4.w*k4.w;
            #pragma unroll
            for (int off = 16; off; off >>= 1) {
                sq += __shfl_xor_sync(0xffffffffu, sq, off);
                sk += __shfl_xor_sync(0xffffffffu, sk, off);
            }
            float rq = rsqrtf(sq + 1e-6f) * qscale;
            float rk = rsqrtf(sk + 1e-6f);
            q4.x*=rq; q4.y*=rq; q4.z*=rq; q4.w*=rq;
            k4.x*=rk; k4.y*=rk; k4.z*=rk; k4.w*=rk;
            *(float4*)&sQ[row*KP + lane*4] = q4;
            *(float4*)&sK[row*KP + lane*4] = k4;
        }
        {
            int row = tid >> 3, j0 = (tid & 7)*4;
            const float* vp = gv + ((size_t)((b*S_ + s0 + row)*H_ + h))*DV_ + vs*DVS + j0;
            float4 v4 = *(const float4*)vp;
            float bb = sbeta[row];
            v4.x*=bb; v4.y*=bb; v4.z*=bb; v4.w*=bb;
            *(float4*)&sU[row*DVS + j0] = v4;
        }
        __syncthreads();

        const float gL = sg_[CH_ - 1];

        // ---- P2b: sdec; transpose K -> sKt; sW = kb*exp(gcs) ----
        if (tid < CH_) sdec[tid] = __expf(gL - sg_[tid]);
        #pragma unroll
        for (int it = 0; it < 4; ++it) {
            int d  = tid & 127;
            int jg = (tid >> 7) + it*4;       // 0..15
            int r0 = jg*4;
            float4 v;
            v.x = sK[(r0+0)*KP + d];
            v.y = sK[(r0+1)*KP + d];
            v.z = sK[(r0+2)*KP + d];
            v.w = sK[(r0+3)*KP + d];
            *(float4*)&sKt[d*TP + r0] = v;
        }
        #pragma unroll
        for (int it = 0; it < 4; ++it) {
            int idx = tid + it*NTHR;          // 0..2047
            int row = idx >> 5, d0 = (idx & 31)*4;
            float s = sbeta[row] * __expf(sg_[row]);
            float4 k4 = *(const float4*)&sK[row*KP + d0];
            k4.x*=s; k4.y*=s; k4.z*=s; k4.w*=s;
            *(float4*)&sW[row*KP + d0] = k4;
        }
        __syncthreads();

        // ---- P3: A = strict_lower((kb) k^T * decay) -> sA ----
        {
            const int wr = warp & 7, wc = warp >> 3;
            const int ly = lane >> 3, lx = lane & 7;
            const int i0 = wr*8 + ly*2;
            const int j0 = wc*32 + lx*4;
            float acc[2][4];
            #pragma unroll
            for (int ii=0; ii<2; ++ii)
                #pragma unroll
                for (int jj=0; jj<4; ++jj) acc[ii][jj] = 0.f;
            for (int d0 = 0; d0 < DK_; d0 += 4) {
                float a_[2][4], b_[4][4];
                *(float4*)a_[0] = *(const float4*)&sK[(i0+0)*KP + d0];
                *(float4*)a_[1] = *(const float4*)&sK[(i0+1)*KP + d0];
                #pragma unroll
                for (int t=0; t<4; ++t)
                    *(float4*)b_[t] = *(const float4*)&sKt[(d0+t)*TP + j0];
                #pragma unroll
                for (int t=0; t<4; ++t)
                    #pragma unroll
                    for (int ii=0; ii<2; ++ii)
                        #pragma unroll
                        for (int jj=0; jj<4; ++jj)
                            acc[ii][jj] += a_[ii][t] * b_[t][jj];
            }
            #pragma unroll
            for (int ii=0; ii<2; ++ii) {
                int i = i0 + ii; float bi = sbeta[i], gi = sg_[i];
                #pragma unroll
                for (int jj=0; jj<4; ++jj) {
                    int j = j0 + jj;
                    sA[i*AP + j] = (i > j) ? acc[ii][jj]*bi*__expf(gi - sg_[j]) : 0.f;
                }
            }
        }
        __syncthreads();

        // ---- P4: blocked forward substitution (I+A) X = [vb | kb*exp(gcs)] ----
        if (tid < 40) {                        // blk 0 diagonal
            int c0 = tid*4;
            #pragma unroll
            for (int i = 1; i < 8; ++i) {
                float4 acc = {0.f,0.f,0.f,0.f};
                for (int l = 0; l < i; ++l) {
                    float a = sA[i*AP + l];
                    float4 x = ldX4(sU, sW, l, c0);
                    acc.x += a*x.x; acc.y += a*x.y; acc.z += a*x.z; acc.w += a*x.w;
                }
                float4 xi = ldX4(sU, sW, i, c0);
                xi.x -= acc.x; xi.y -= acc.y; xi.z -= acc.z; xi.w -= acc.w;
                stX4(sU, sW, i, c0, xi);
            }
        }
        __syncthreads();
        for (int blk = 1; blk < 8; ++blk) {
            const int R0 = blk*8;
            if (tid < 320) {                   // off-diagonal rank update
                int r = tid/40, cg = tid%40, row = R0 + r, c0 = cg*4;
                float4 acc = {0.f,0.f,0.f,0.f};
                for (int l0 = 0; l0 < R0; l0 += 4) {
                    float a_[4]; *(float4*)a_ = *(const float4*)&sA[row*AP + l0];
                    #pragma unroll
                    for (int t = 0; t < 4; ++t) {
                        float4 x = ldX4(sU, sW, l0 + t, c0);
                        acc.x += a_[t]*x.x; acc.y += a_[t]*x.y;
                        acc.z += a_[t]*x.z; acc.w += a_[t]*x.w;
                    }
                }
                float4 xr = ldX4(sU, sW, row, c0);
                xr.x -= acc.x; xr.y -= acc.y; xr.z -= acc.z; xr.w -= acc.w;
                stX4(sU, sW, row, c0, xr);
            }
            __syncthreads();
            if (tid < 40) {                    // diagonal 8x8 serial solve
                int c0 = tid*4;
                #pragma unroll
                for (int i = 1; i < 8; ++i) {
                    int row = R0 + i;
                    float4 acc = {0.f,0.f,0.f,0.f};
                    for (int l = 0; l < i; ++l) {
                        float a = sA[row*AP + R0 + l];
                        float4 x = ldX4(sU, sW, R0 + l, c0);
                        acc.x += a*x.x; acc.y += a*x.y; acc.z += a*x.z; acc.w += a*x.w;
                    }
                    float4 xi = ldX4(sU, sW, row, c0);
                    xi.x -= acc.x; xi.y -= acc.y; xi.z -= acc.z; xi.w -= acc.w;
                    stX4(sU, sW, row, c0, xi);
                }
            }
            __syncthreads();
        }

        // ---- P5: attn -> sA ; v_new = u - kcd @ state -> sU ----
        {
            const int wr = warp & 7, wc = warp >> 3;
            const int ly = lane >> 3, lx = lane & 7;
            const int i0 = wr*8 + ly*2;
            const int j0 = wc*32 + lx*4;
            float acc[2][4];
            #pragma unroll
            for (int ii=0; ii<2; ++ii)
                #pragma unroll
                for (int jj=0; jj<4; ++jj) acc[ii][jj] = 0.f;
            for (int d0 = 0; d0 < DK_; d0 += 4) {
                float a_[2][4], b_[4][4];
                *(float4*)a_[0] = *(const float4*)&sQ[(i0+0)*KP + d0];
                *(float4*)a_[1] = *(const float4*)&sQ[(i0+1)*KP + d0];
                #pragma unroll
                for (int t=0; t<4; ++t)
                    *(float4*)b_[t] = *(const float4*)&sKt[(d0+t)*TP + j0];
                #pragma unroll
                for (int t=0; t<4; ++t)
                    #pragma unroll
                    for (int ii=0; ii<2; ++ii)
                        #pragma unroll
                        for (int jj=0; jj<4; ++jj)
                            acc[ii][jj] += a_[ii][t] * b_[t][jj];
            }
            #pragma unroll
            for (int ii=0; ii<2; ++ii) {
                int i = i0 + ii; float gi = sg_[i];
                #pragma unroll
                for (int jj=0; jj<4; ++jj) {
                    int j = j0 + jj;
                    sA[i*AP + j] = (i >= j) ? acc[ii][jj]*__expf(gi - sg_[j]) : 0.f;
                }
            }
        }
        {
            int row = tid >> 3, j0 = (tid & 7)*4;
            float vn[4]; *(float4*)vn = *(const float4*)&sU[row*DVS + j0];
            for (int d0 = 0; d0 < DK_; d0 += 4) {
                float w_[4], s_[4][4];
                *(float4*)w_ = *(const float4*)&sW[row*KP + d0];
                #pragma unroll
                for (int t=0; t<4; ++t)
                    *(float4*)s_[t] = *(const float4*)&sState[(d0+t)*DVS + j0];
                #pragma unroll
                for (int t=0; t<4; ++t)
                    #pragma unroll
                    for (int c=0; c<4; ++c) vn[c] -= w_[t]*s_[t][c];
            }
            *(float4*)&sU[row*DVS + j0] = vn[0] == vn[0] ? *(float4*)vn : *(float4*)vn;
        }
        __syncthreads();

        // ---- P6: o = (q*exp(gcs)) @ state + attn @ v_new -> gmem ----
        {
            int row = tid >> 3, j0 = (tid & 7)*4;
            float o_[4] = {0.f,0.f,0.f,0.f};
            for (int d0 = 0; d0 < DK_; d0 += 4) {
                float q_[4], s_[4][4];
                *(float4*)q_ = *(const float4*)&sQ[row*KP + d0];
                #pragma unroll
                for (int t=0; t<4; ++t)
                    *(float4*)s_[t] = *(const float4*)&sState[(d0+t)*DVS + j0];
                #pragma unroll
                for (int t=0; t<4; ++t)
                    #pragma unroll
                    for (int c=0; c<4; ++c) o_[c] += q_[t]*s_[t][c];
            }
            float eg = __expf(sg_[row]);
            #pragma unroll
            for (int c=0; c<4; ++c) o_[c] *= eg;
            for (int d0 = 0; d0 < CH_; d0 += 4) {
                float a_[4], u_[4][4];
                *(float4*)a_ = *(const float4*)&sA[row*AP + d0];
                #pragma unroll
                for (int t=0; t<4; ++t)
                    *(float4*)u_[t] = *(const float4*)&sU[(d0+t)*DVS + j0];
                #pragma unroll
                for (int t=0; t<4; ++t)
                    #pragma unroll
                    for (int c=0; c<4; ++c) o_[c] += a_[t]*u_[t][c];
            }
            float* op = gout + ((size_t)((b*S_ + s0 + row)*H_ + h))*DV_ + vs*DVS + j0;
            *(float4*)op = *(float4*)o_;
        }
        __syncthreads();

        // ---- P7: state = state*exp(gL) + (k*exp(gL-gcs))^T @ v_new ----
        {
            int j0 = (tid & 7)*4;
            int d0 = (tid >> 3)*2;
            float acc[2][4];
            #pragma unroll
            for (int dd=0; dd<2; ++dd)
                #pragma unroll
                for (int c=0; c<4; ++c) acc[dd][c] = 0.f;
            for (int r0 = 0; r0 < CH_; r0 += 4) {
                float dec_[4], kt_[2][4], u_[4][4];
                *(float4*)dec_  = *(const float4*)&sdec[r0];
                *(float4*)kt_[0] = *(const float4*)&sKt[(d0+0)*TP + r0];
                *(float4*)kt_[1] = *(const float4*)&sKt[(d0+1)*TP + r0];
                #pragma unroll
                for (int rr=0; rr<4; ++rr)
                    *(float4*)u_[rr] = *(const float4*)&sU[(r0+rr)*DVS + j0];
                float kd[2][4];
                #pragma unroll
                for (int dd=0; dd<2; ++dd)
                    #pragma unroll
                    for (int rr=0; rr<4; ++rr) kd[dd][rr] = kt_[dd][rr]*dec_[rr];
                #pragma unroll
                for (int dd=0; dd<2; ++dd)
                    #pragma unroll
                    for (int rr=0; rr<4; ++rr)
                        #pragma unroll
                        for (int c=0; c<4; ++c) acc[dd][c] += kd[dd][rr]*u_[rr][c];
            }
            const float eL = __expf(gL);
            #pragma unroll
            for (int dd=0; dd<2; ++dd) {
                float st[4];
                *(float4*)st = *(const float4*)&sState[(d0+dd)*DVS + j0];
                #pragma unroll
                for (int c=0; c<4; ++c) st[c] = st[c]*eL + acc[dd][c];
                *(float4*)&sState[(d0+dd)*DVS + j0] = *(float4*)st;
            }
        }
        __syncthreads();
    }
}

extern "C" void kernel_launch(void* const* d_in, const int* in_sizes, int n_in,
                              void* d_out, int out_size) {
    (void)in_sizes; (void)n_in; (void)out_size;
    const float* q    = (const float*)d_in[0];
    const float* k    = (const float*)d_in[1];
    const float* v    = (const float*)d_in[2];
    const float* g    = (const float*)d_in[3];
    const float* beta = (const float*)d_in[4];
    float* out = (float*)d_out;

    size_t smem = (size_t)SM_FLOATS * sizeof(float);   // ~174.8 KB
    cudaFuncSetAttribute(gdr_kernel, cudaFuncAttributeMaxDynamicSharedMemorySize, (int)smem);

    dim3 grid(NSPLIT, H_, B_);
    gdr_kernel<<<grid, NTHR, smem>>>(q, k, v, g, beta, out);
}

// round 6
// speedup vs baseline: 1.9326x; 1.8298x over previous
#include <cuda_runtime.h>

#define B_ 2
#define S_ 4096
#define H_ 16
#define DK_ 128
#define DV_ 128
#define CH_ 64
#define NCH (S_ / CH_)
#define NBH (B_ * H_)
#define NSPLIT 4
#define DVS 32
#define NTHR 512

// ---------------- scratch (static device globals; no runtime alloc) ----------------
__device__ float g_u  [(size_t)NBH * NCH * CH_ * DV_];  // slice-blocked [bhn][vs][64][32]
__device__ float g_w  [(size_t)NBH * NCH * CH_ * DK_];  // kcd  [bhn][64][128]
__device__ float g_qg [(size_t)NBH * NCH * CH_ * DK_];  // qn*scale*exp(gcs) [bhn][64][128]
__device__ float g_kdt[(size_t)NBH * NCH * DK_ * CH_];  // k^T * exp(gL-gcs) [bhn][128][64]
__device__ float g_att[(size_t)NBH * NCH * CH_ * CH_];  // attn [bhn][64][64]
__device__ float g_eL [(size_t)NBH * NCH];              // exp(gL)

// ================================ KERNEL 1 ================================
// grid (NCH, H, B), 512 threads. Per (b,h,chunk): normalize, build A/attn,
// solve (I+A)X=[Vb | Kb*exp(gcs)], prefold decays, write scratch.

#define KP1 132
#define TP1 68
#define AP1 68
#define SM1_FLOATS (2*CH_*KP1 + DK_*TP1 + 2*CH_*DK_ + CH_*AP1 + 8*64 + 3*CH_)

__device__ __forceinline__ float4 ldX(const float* sXv, const float* sXw, int r, int c0) {
    if (c0 < DK_) return *(const float4*)&sXv[r*DK_ + c0];
    return *(const float4*)&sXw[r*DK_ + (c0 - DK_)];
}
__device__ __forceinline__ void stX(float* sXv, float* sXw, int r, int c0, float4 v) {
    if (c0 < DK_) *(float4*)&sXv[r*DK_ + c0] = v;
    else          *(float4*)&sXw[r*DK_ + (c0 - DK_)] = v;
}

__global__ __launch_bounds__(NTHR, 1)
void gdr_prep(const float* __restrict__ gq, const float* __restrict__ gk,
              const float* __restrict__ gv, const float* __restrict__ gg,
              const float* __restrict__ gb)
{
    extern __shared__ float sm[];
    float* sK    = sm;                 // [64][132]
    float* sQ    = sK + CH_*KP1;       // [64][132]
    float* sKt   = sQ + CH_*KP1;       // [128][68]
    float* sXv   = sKt + DK_*TP1;      // [64][128]  V*beta -> u
    float* sXw   = sXv + CH_*DK_;      // [64][128]  K*beta*exp(gcs) -> kcd
    float* sA    = sXw + CH_*DK_;      // [64][68]
    float* sTinv = sA + CH_*AP1;       // [8][8][8]
    float* sg_   = sTinv + 8*64;       // [64]
    float* sbeta = sg_ + CH_;
    float* sdec  = sbeta + CH_;

    const int n = blockIdx.x, h = blockIdx.y, b = blockIdx.z;
    const int s0 = n * CH_;
    const int tid = threadIdx.x, lane = tid & 31, warp = tid >> 5;
    const int bhn = (b*H_ + h)*NCH + n;
    const size_t cb = (size_t)bhn * (CH_*DK_);
    const size_t ab = (size_t)bhn * (CH_*CH_);
    const float qscale = 0.08838834764831845f;

    // P1: raw g, beta
    if (tid < CH_) {
        int idx = (b*S_ + s0 + tid)*H_ + h;
        sg_[tid]   = gg[idx];
        sbeta[tid] = gb[idx];
    }
    __syncthreads();

    // P2: scan g -> gcs (warp0); load+normalize Q,K; V*beta -> sXv
    if (warp == 0) {
        float a0 = sg_[lane], a1 = sg_[lane + 32];
        #pragma unroll
        for (int off = 1; off < 32; off <<= 1) {
            float t = __shfl_up_sync(0xffffffffu, a0, off);
            if (lane >= off) a0 += t;
        }
        #pragma unroll
        for (int off = 1; off < 32; off <<= 1) {
            float t = __shfl_up_sync(0xffffffffu, a1, off);
            if (lane >= off) a1 += t;
        }
        a1 += __shfl_sync(0xffffffffu, a0, 31);
        sg_[lane] = a0; sg_[lane + 32] = a1;
    }
    #pragma unroll
    for (int r4 = 0; r4 < 4; ++r4) {
        int row = warp*4 + r4;
        const float* qp = gq + ((size_t)((b*S_ + s0 + row)*H_ + h))*DK_;
        const float* kp = gk + ((size_t)((b*S_ + s0 + row)*H_ + h))*DK_;
        float4 q4 = *(const float4*)(qp + lane*4);
        float4 k4 = *(const float4*)(kp + lane*4);
        float sq = q4.x*q4.x + q4.y*q4.y + q4.z*q4.z + q4.w*q4.w;
        float sk = k4.x*k4.x + k4.y*k4.y + k4.z*k4.z + k4.w*k4.w;
        #pragma unroll
        for (int off = 16; off; off >>= 1) {
            sq += __shfl_xor_sync(0xffffffffu, sq, off);
            sk += __shfl_xor_sync(0xffffffffu, sk, off);
        }
        float rq = rsqrtf(sq + 1e-6f) * qscale;
        float rk = rsqrtf(sk + 1e-6f);
        q4.x*=rq; q4.y*=rq; q4.z*=rq; q4.w*=rq;
        k4.x*=rk; k4.y*=rk; k4.z*=rk; k4.w*=rk;
        *(float4*)&sQ[row*KP1 + lane*4] = q4;
        *(float4*)&sK[row*KP1 + lane*4] = k4;
    }
    #pragma unroll
    for (int it = 0; it < 4; ++it) {
        int idx = tid + it*NTHR;
        int row = idx >> 5, dq = (idx & 31)*4;
        const float* vp = gv + ((size_t)((b*S_ + s0 + row)*H_ + h))*DV_ + dq;
        float4 v4 = *(const float4*)vp;
        float bb = sbeta[row];
        v4.x*=bb; v4.y*=bb; v4.z*=bb; v4.w*=bb;
        *(float4*)&sXv[row*DK_ + dq] = v4;
    }
    __syncthreads();

    const float gL = sg_[CH_ - 1];

    // P3: sdec; transpose K -> sKt; eL store
    if (tid < CH_) sdec[tid] = __expf(gL - sg_[tid]);
    if (tid == 0) g_eL[bhn] = __expf(gL);
    #pragma unroll
    for (int it = 0; it < 4; ++it) {
        int d  = tid & 127;
        int r0 = ((tid >> 7) + it*4)*4;
        float4 v;
        v.x = sK[(r0+0)*KP1 + d];
        v.y = sK[(r0+1)*KP1 + d];
        v.z = sK[(r0+2)*KP1 + d];
        v.w = sK[(r0+3)*KP1 + d];
        *(float4*)&sKt[d*TP1 + r0] = v;
    }
    __syncthreads();

    // P4: A = strict_lower(kb k^T * decay); sXw = kb*exp(gcs); qg store; kdt store
    {
        const int wr = warp & 7, wc = warp >> 3;
        const int ly = lane >> 3, lx = lane & 7;
        const int i0 = wr*8 + ly*2;
        const int j0 = wc*32 + lx*4;
        float acc[2][4];
        #pragma unroll
        for (int ii=0; ii<2; ++ii)
            #pragma unroll
            for (int jj=0; jj<4; ++jj) acc[ii][jj] = 0.f;
        #pragma unroll 8
        for (int d0 = 0; d0 < DK_; d0 += 4) {
            float a_[2][4], b_[4][4];
            *(float4*)a_[0] = *(const float4*)&sK[(i0+0)*KP1 + d0];
            *(float4*)a_[1] = *(const float4*)&sK[(i0+1)*KP1 + d0];
            #pragma unroll
            for (int t=0; t<4; ++t)
                *(float4*)b_[t] = *(const float4*)&sKt[(d0+t)*TP1 + j0];
            #pragma unroll
            for (int t=0; t<4; ++t)
                #pragma unroll
                for (int ii=0; ii<2; ++ii)
                    #pragma unroll
                    for (int jj=0; jj<4; ++jj)
                        acc[ii][jj] += a_[ii][t] * b_[t][jj];
        }
        #pragma unroll
        for (int ii=0; ii<2; ++ii) {
            int i = i0 + ii; float bi = sbeta[i], gi = sg_[i];
            #pragma unroll
            for (int jj=0; jj<4; ++jj) {
                int j = j0 + jj;
                sA[i*AP1 + j] = (i > j) ? acc[ii][jj]*bi*__expf(gi - sg_[j]) : 0.f;
            }
        }
    }
    #pragma unroll
    for (int it = 0; it < 4; ++it) {
        int idx = tid + it*NTHR;
        int row = idx >> 5, dq = (idx & 31)*4;
        float se = __expf(sg_[row]);
        float sw = sbeta[row] * se;
        float4 k4 = *(const float4*)&sK[row*KP1 + dq];
        k4.x*=sw; k4.y*=sw; k4.z*=sw; k4.w*=sw;
        *(float4*)&sXw[row*DK_ + dq] = k4;
        float4 q4 = *(const float4*)&sQ[row*KP1 + dq];
        q4.x*=se; q4.y*=se; q4.z*=se; q4.w*=se;
        *(float4*)&g_qg[cb + row*DK_ + dq] = q4;
    }
    #pragma unroll
    for (int it = 0; it < 4; ++it) {
        int idx = tid + it*NTHR;
        int d = idx >> 4, r0 = (idx & 15)*4;
        float4 kt = *(const float4*)&sKt[d*TP1 + r0];
        kt.x *= sdec[r0+0]; kt.y *= sdec[r0+1]; kt.z *= sdec[r0+2]; kt.w *= sdec[r0+3];
        *(float4*)&g_kdt[cb + d*CH_ + r0] = kt;
    }
    __syncthreads();

    // P5: attn GEMM -> gmem (incl diag); warps 0-7 then invert diag 8x8 blocks
    {
        const int wr = warp & 7, wc = warp >> 3;
        const int ly = lane >> 3, lx = lane & 7;
        const int i0 = wr*8 + ly*2;
        const int j0 = wc*32 + lx*4;
        float acc[2][4];
        #pragma unroll
        for (int ii=0; ii<2; ++ii)
            #pragma unroll
            for (int jj=0; jj<4; ++jj) acc[ii][jj] = 0.f;
        #pragma unroll 8
        for (int d0 = 0; d0 < DK_; d0 += 4) {
            float a_[2][4], b_[4][4];
            *(float4*)a_[0] = *(const float4*)&sQ[(i0+0)*KP1 + d0];
            *(float4*)a_[1] = *(const float4*)&sQ[(i0+1)*KP1 + d0];
            #pragma unroll
            for (int t=0; t<4; ++t)
                *(float4*)b_[t] = *(const float4*)&sKt[(d0+t)*TP1 + j0];
            #pragma unroll
            for (int t=0; t<4; ++t)
                #pragma unroll
                for (int ii=0; ii<2; ++ii)
                    #pragma unroll
                    for (int jj=0; jj<4; ++jj)
                        acc[ii][jj] += a_[ii][t] * b_[t][jj];
        }
        #pragma unroll
        for (int ii=0; ii<2; ++ii) {
            int i = i0 + ii; float gi = sg_[i];
            float4 o;
            o.x = (i >= j0+0) ? acc[ii][0]*__expf(gi - sg_[j0+0]) : 0.f;
            o.y = (i >= j0+1) ? acc[ii][1]*__expf(gi - sg_[j0+1]) : 0.f;
            o.z = (i >= j0+2) ? acc[ii][2]*__expf(gi - sg_[j0+2]) : 0.f;
            o.w = (i >= j0+3) ? acc[ii][3]*__expf(gi - sg_[j0+3]) : 0.f;
            *(float4*)&g_att[ab + i*CH_ + j0] = o;
        }
    }
    if (warp < 8 && lane < 8) {
        const int blk = warp, R0 = blk*8, c = lane;
        float x[8];
        #pragma unroll
        for (int i = 0; i < 8; ++i) {
            float v = (i == c) ? 1.f : 0.f;
            #pragma unroll
            for (int l = 0; l < 8; ++l)
                if (l < i) v -= sA[(R0+i)*AP1 + (R0+l)] * x[l];
            x[i] = v;
        }
        #pragma unroll
        for (int i = 0; i < 8; ++i) sTinv[blk*64 + i*8 + c] = x[i];
    }
    __syncthreads();

    // P6: blocked forward substitution with parallel Tinv apply
    {
        const int i = tid >> 6;                 // 0..7 row within block
        const int c0 = (tid & 63) * 4;          // 0..252
        // blk 0: apply
        float4 acc = {0.f,0.f,0.f,0.f};
        #pragma unroll
        for (int l = 0; l < 8; ++l) {
            float t = sTinv[0*64 + i*8 + l];
            float4 x = ldX(sXv, sXw, l, c0);
            acc.x += t*x.x; acc.y += t*x.y; acc.z += t*x.z; acc.w += t*x.w;
        }
        __syncthreads();
        stX(sXv, sXw, i, c0, acc);
        __syncthreads();
        for (int blk = 1; blk < 8; ++blk) {
            const int R0 = blk*8, row = R0 + i;
            // rank update (reads rows < R0, writes own row)
            float4 s = ldX(sXv, sXw, row, c0);
            #pragma unroll 4
            for (int m = 0; m < R0; ++m) {
                float a = sA[row*AP1 + m];
                float4 x = ldX(sXv, sXw, m, c0);
                s.x -= a*x.x; s.y -= a*x.y; s.z -= a*x.z; s.w -= a*x.w;
            }
            stX(sXv, sXw, row, c0, s);
            __syncthreads();
            // apply Tinv
            float4 ac = {0.f,0.f,0.f,0.f};
            #pragma unroll
            for (int l = 0; l < 8; ++l) {
                float t = sTinv[blk*64 + i*8 + l];
                float4 x = ldX(sXv, sXw, R0 + l, c0);
                ac.x += t*x.x; ac.y += t*x.y; ac.z += t*x.z; ac.w += t*x.w;
            }
            __syncthreads();
            stX(sXv, sXw, row, c0, ac);
            __syncthreads();
        }
    }

    // P7: store u (slice-blocked) and kcd
    #pragma unroll
    for (int it = 0; it < 4; ++it) {
        int idx = tid + it*NTHR;
        int row = idx >> 5, c0 = (idx & 31)*4;
        float4 uv = *(const float4*)&sXv[row*DK_ + c0];
        int vsb = c0 >> 5, jj = c0 & 31;
        *(float4*)&g_u[cb + (size_t)vsb*(CH_*DVS) + row*DVS + jj] = uv;
        float4 wv = *(const float4*)&sXw[row*DK_ + c0];
        *(float4*)&g_w[cb + row*DK_ + c0] = wv;
    }
}

// ================================ KERNEL 2 ================================
// grid (NSPLIT, H, B) = 128 blocks, 512 threads. Sequential scan over chunks.

#define WP2 132
#define TP2 68
#define AP2 68
#define SM2_FLOATS (2*CH_*WP2 + DK_*TP2 + CH_*AP2 + CH_*DVS + DK_*DVS)

__global__ __launch_bounds__(NTHR, 1)
void gdr_scan(float* __restrict__ gout)
{
    extern __shared__ float sm[];
    float* sW    = sm;                 // [64][132] kcd
    float* sQg   = sW + CH_*WP2;       // [64][132]
    float* sKdT  = sQg + CH_*WP2;      // [128][68]
    float* sAttn = sKdT + DK_*TP2;     // [64][68]
    float* sU    = sAttn + CH_*AP2;    // [64][32]  u -> v_new
    float* sState= sU + CH_*DVS;       // [128][32]

    const int vs = blockIdx.x, h = blockIdx.y, b = blockIdx.z;
    const int tid = threadIdx.x;
    const int bh = b*H_ + h;

    for (int i = tid; i < DK_*DVS; i += NTHR) sState[i] = 0.f;

    const int rA  = tid >> 3, jA = (tid & 7)*4;      // v_new / o layout
    const int dC  = (tid >> 3)*2, jC = (tid & 7)*4;  // state-update layout

    for (int n = 0; n < NCH; ++n) {
        const size_t cb = (size_t)(bh*NCH + n) * (CH_*DK_);
        const size_t ab = (size_t)(bh*NCH + n) * (CH_*CH_);
        const int s0 = n * CH_;

        // ---- stage ----
        #pragma unroll
        for (int it = 0; it < 4; ++it) {
            int idx = tid + it*NTHR;
            int row = idx >> 5, dq = (idx & 31)*4;
            *(float4*)&sW[row*WP2 + dq]  = *(const float4*)&g_w[cb + row*DK_ + dq];
            *(float4*)&sQg[row*WP2 + dq] = *(const float4*)&g_qg[cb + row*DK_ + dq];
        }
        #pragma unroll
        for (int it = 0; it < 4; ++it) {
            int idx = tid + it*NTHR;
            int d = idx >> 4, r0 = (idx & 15)*4;
            *(float4*)&sKdT[d*TP2 + r0] = *(const float4*)&g_kdt[cb + d*CH_ + r0];
        }
        #pragma unroll
        for (int it = 0; it < 2; ++it) {
            int idx = tid + it*NTHR;
            int row = idx >> 4, c0 = (idx & 15)*4;
            *(float4*)&sAttn[row*AP2 + c0] = *(const float4*)&g_att[ab + row*CH_ + c0];
        }
        {
            int row = tid >> 3, jq = (tid & 7)*4;
            *(float4*)&sU[row*DVS + jq] =
                *(const float4*)&g_u[cb + (size_t)vs*(CH_*DVS) + row*DVS + jq];
        }
        __syncthreads();

        // ---- v_new = u - kcd @ state ----
        {
            float vn[4];
            *(float4*)vn = *(const float4*)&sU[rA*DVS + jA];
            #pragma unroll 8
            for (int d0 = 0; d0 < DK_; d0 += 4) {
                float w_[4], s_[4][4];
                *(float4*)w_ = *(const float4*)&sW[rA*WP2 + d0];
                #pragma unroll
                for (int t=0; t<4; ++t)
                    *(float4*)s_[t] = *(const float4*)&sState[(d0+t)*DVS + jA];
                #pragma unroll
                for (int t=0; t<4; ++t)
                    #pragma unroll
                    for (int c=0; c<4; ++c) vn[c] -= w_[t]*s_[t][c];
            }
            *(float4*)&sU[rA*DVS + jA] = *(float4*)vn;
        }
        __syncthreads();

        // ---- o = qg @ state + attn @ v_new ----
        {
            float o_[4] = {0.f,0.f,0.f,0.f};
            #pragma unroll 8
            for (int d0 = 0; d0 < DK_; d0 += 4) {
                float q_[4], s_[4][4];
                *(float4*)q_ = *(const float4*)&sQg[rA*WP2 + d0];
                #pragma unroll
                for (int t=0; t<4; ++t)
                    *(float4*)s_[t] = *(const float4*)&sState[(d0+t)*DVS + jA];
                #pragma unroll
                for (int t=0; t<4; ++t)
                    #pragma unroll
                    for (int c=0; c<4; ++c) o_[c] += q_[t]*s_[t][c];
            }
            #pragma unroll 4
            for (int c0 = 0; c0 < CH_; c0 += 4) {
                float a_[4], u_[4][4];
                *(float4*)a_ = *(const float4*)&sAttn[rA*AP2 + c0];
                #pragma unroll
                for (int t=0; t<4; ++t)
                    *(float4*)u_[t] = *(const float4*)&sU[(c0+t)*DVS + jA];
                #pragma unroll
                for (int t=0; t<4; ++t)
                    #pragma unroll
                    for (int c=0; c<4; ++c) o_[c] += a_[t]*u_[t][c];
            }
            float* op = gout + ((size_t)((b*S_ + s0 + rA)*H_ + h))*DV_ + vs*DVS + jA;
            *(float4*)op = *(float4*)o_;
        }
        __syncthreads();

        // ---- state = state*eL + kdecT @ v_new ----
        {
            const float eL = g_eL[bh*NCH + n];
            float acc[2][4];
            #pragma unroll
            for (int dd=0; dd<2; ++dd)
                #pragma unroll
                for (int c=0; c<4; ++c) acc[dd][c] = 0.f;
            #pragma unroll 4
            for (int r0 = 0; r0 < CH_; r0 += 4) {
                float kd[2][4], u_[4][4];
                *(float4*)kd[0] = *(const float4*)&sKdT[(dC+0)*TP2 + r0];
                *(float4*)kd[1] = *(const float4*)&sKdT[(dC+1)*TP2 + r0];
                #pragma unroll
                for (int rr=0; rr<4; ++rr)
                    *(float4*)u_[rr] = *(const float4*)&sU[(r0+rr)*DVS + jC];
                #pragma unroll
                for (int dd=0; dd<2; ++dd)
                    #pragma unroll
                    for (int rr=0; rr<4; ++rr)
                        #pragma unroll
                        for (int c=0; c<4; ++c) acc[dd][c] += kd[dd][rr]*u_[rr][c];
            }
            #pragma unroll
            for (int dd=0; dd<2; ++dd) {
                float st[4];
                *(float4*)st = *(const float4*)&sState[(dC+dd)*DVS + jC];
                #pragma unroll
                for (int c=0; c<4; ++c) st[c] = st[c]*eL + acc[dd][c];
                *(float4*)&sState[(dC+dd)*DVS + jC] = *(float4*)st;
            }
        }
        __syncthreads();
    }
}

extern "C" void kernel_launch(void* const* d_in, const int* in_sizes, int n_in,
                              void* d_out, int out_size) {
    (void)in_sizes; (void)n_in; (void)out_size;
    const float* q    = (const float*)d_in[0];
    const float* k    = (const float*)d_in[1];
    const float* v    = (const float*)d_in[2];
    const float* g    = (const float*)d_in[3];
    const float* beta = (const float*)d_in[4];
    float* out = (float*)d_out;

    size_t smem1 = (size_t)SM1_FLOATS * sizeof(float);   // ~188 KB
    size_t smem2 = (size_t)SM2_FLOATS * sizeof(float);   // ~144 KB
    cudaFuncSetAttribute(gdr_prep, cudaFuncAttributeMaxDynamicSharedMemorySize, (int)smem1);
    cudaFuncSetAttribute(gdr_scan, cudaFuncAttributeMaxDynamicSharedMemorySize, (int)smem2);

    dim3 grid1(NCH, H_, B_);
    gdr_prep<<<grid1, NTHR, smem1>>>(q, k, v, g, beta);

    dim3 grid2(NSPLIT, H_, B_);
    gdr_scan<<<grid2, NTHR, smem2>>>(out);
}

// round 7
// speedup vs baseline: 2.5780x; 1.3340x over previous
#include <cuda_runtime.h>

#define B_ 2
#define S_ 4096
#define H_ 16
#define DK_ 128
#define DV_ 128
#define CH_ 64
#define NCH (S_ / CH_)
#define NBH (B_ * H_)
#define NSPLIT 4
#define DVS 32
#define NTHR 512

typedef unsigned long long u64;

__device__ __forceinline__ void fma2(u64& d, u64 a, u64 b) {
    asm("fma.rn.f32x2 %0, %1, %2, %0;" : "+l"(d) : "l"(a), "l"(b));
}
__device__ __forceinline__ float hsum2(u64 v) {
    float lo, hi;
    asm("mov.b64 {%0,%1}, %2;" : "=f"(lo), "=f"(hi) : "l"(v));
    return lo + hi;
}

// ---------------- scratch ----------------
__device__ float g_u  [(size_t)NBH * NCH * CH_ * DV_];  // [bhn][vs][64][32]
__device__ float g_w  [(size_t)NBH * NCH * CH_ * DK_];  // kcd  [bhn][64][128]
__device__ float g_qg [(size_t)NBH * NCH * CH_ * DK_];  // q*scale*exp(gcs)
__device__ float g_kdt[(size_t)NBH * NCH * DK_ * CH_];  // k^T*exp(gL-gcs) [d][r]
__device__ float g_att[(size_t)NBH * NCH * CH_ * CH_];  // attn (incl diag)
__device__ float g_eL [(size_t)NBH * NCH];

// ================================ KERNEL 1 ================================
#define KP1 132
#define TP1 68
#define AP1 68
#define SM1_FLOATS (2*CH_*KP1 + DK_*TP1 + 2*CH_*DK_ + CH_*AP1 + 8*64 + 5*CH_)

__device__ __forceinline__ float4 ldX(const float* sXv, const float* sXw, int r, int c0) {
    if (c0 < DK_) return *(const float4*)&sXv[r*DK_ + c0];
    return *(const float4*)&sXw[r*DK_ + (c0 - DK_)];
}
__device__ __forceinline__ void stX(float* sXv, float* sXw, int r, int c0, float4 v) {
    if (c0 < DK_) *(float4*)&sXv[r*DK_ + c0] = v;
    else          *(float4*)&sXw[r*DK_ + (c0 - DK_)] = v;
}

__global__ __launch_bounds__(NTHR, 1)
void gdr_prep(const float* __restrict__ gq, const float* __restrict__ gk,
              const float* __restrict__ gv, const float* __restrict__ gg,
              const float* __restrict__ gb)
{
    extern __shared__ float sm[];
    float* sK    = sm;                 // [64][132]
    float* sQ    = sK + CH_*KP1;       // [64][132]
    float* sKt   = sQ + CH_*KP1;       // [128][68]
    float* sXv   = sKt + DK_*TP1;      // [64][128]
    float* sXw   = sXv + CH_*DK_;      // [64][128]
    float* sA    = sXw + CH_*DK_;      // [64][68]
    float* sTinv = sA + CH_*AP1;       // [8][8][8]
    float* sg_   = sTinv + 8*64;
    float* sbeta = sg_ + CH_;
    float* sdec  = sbeta + CH_;
    float* sEg   = sdec + CH_;         // exp(gcs)
    float* sEgi  = sEg + CH_;          // exp(-gcs)

    const int n = blockIdx.x, h = blockIdx.y, b = blockIdx.z;
    const int s0 = n * CH_;
    const int tid = threadIdx.x, lane = tid & 31, warp = tid >> 5;
    const int bhn = (b*H_ + h)*NCH + n;
    const size_t cb = (size_t)bhn * (CH_*DK_);
    const size_t ab = (size_t)bhn * (CH_*CH_);
    const float qscale = 0.08838834764831845f;

    // P1
    if (tid < CH_) {
        int idx = (b*S_ + s0 + tid)*H_ + h;
        sg_[tid]   = gg[idx];
        sbeta[tid] = gb[idx];
    }
    __syncthreads();

    // P2
    if (warp == 0) {
        float a0 = sg_[lane], a1 = sg_[lane + 32];
        #pragma unroll
        for (int off = 1; off < 32; off <<= 1) {
            float t = __shfl_up_sync(0xffffffffu, a0, off);
            if (lane >= off) a0 += t;
        }
        #pragma unroll
        for (int off = 1; off < 32; off <<= 1) {
            float t = __shfl_up_sync(0xffffffffu, a1, off);
            if (lane >= off) a1 += t;
        }
        a1 += __shfl_sync(0xffffffffu, a0, 31);
        sg_[lane] = a0; sg_[lane + 32] = a1;
    }
    #pragma unroll
    for (int r4 = 0; r4 < 4; ++r4) {
        int row = warp*4 + r4;
        const float* qp = gq + ((size_t)((b*S_ + s0 + row)*H_ + h))*DK_;
        const float* kp = gk + ((size_t)((b*S_ + s0 + row)*H_ + h))*DK_;
        float4 q4 = *(const float4*)(qp + lane*4);
        float4 k4 = *(const float4*)(kp + lane*4);
        float sq = q4.x*q4.x + q4.y*q4.y + q4.z*q4.z + q4.w*q4.w;
        float sk = k4.x*k4.x + k4.y*k4.y + k4.z*k4.z + k4.w*k4.w;
        #pragma unroll
        for (int off = 16; off; off >>= 1) {
            sq += __shfl_xor_sync(0xffffffffu, sq, off);
            sk += __shfl_xor_sync(0xffffffffu, sk, off);
        }
        float rq = rsqrtf(sq + 1e-6f) * qscale;
        float rk = rsqrtf(sk + 1e-6f);
        q4.x*=rq; q4.y*=rq; q4.z*=rq; q4.w*=rq;
        k4.x*=rk; k4.y*=rk; k4.z*=rk; k4.w*=rk;
        *(float4*)&sQ[row*KP1 + lane*4] = q4;
        *(float4*)&sK[row*KP1 + lane*4] = k4;
    }
    #pragma unroll
    for (int it = 0; it < 4; ++it) {
        int idx = tid + it*NTHR;
        int row = idx >> 5, dq = (idx & 31)*4;
        const float* vp = gv + ((size_t)((b*S_ + s0 + row)*H_ + h))*DV_ + dq;
        float4 v4 = *(const float4*)vp;
        float bb = sbeta[row];
        v4.x*=bb; v4.y*=bb; v4.z*=bb; v4.w*=bb;
        *(float4*)&sXv[row*DK_ + dq] = v4;
    }
    __syncthreads();

    const float gL = sg_[CH_ - 1];

    // P3: tables, sdec, transpose, sXw, qg, kdt
    if (tid < CH_) {
        float e = __expf(sg_[tid]);
        sEg[tid]  = e;
        sEgi[tid] = 1.f / e;
        sdec[tid] = __expf(gL - sg_[tid]);
    }
    if (tid == 0) g_eL[bhn] = __expf(gL);
    #pragma unroll
    for (int it = 0; it < 4; ++it) {
        int d  = tid & 127;
        int r0 = ((tid >> 7) + it*4)*4;
        float4 v;
        v.x = sK[(r0+0)*KP1 + d];
        v.y = sK[(r0+1)*KP1 + d];
        v.z = sK[(r0+2)*KP1 + d];
        v.w = sK[(r0+3)*KP1 + d];
        *(float4*)&sKt[d*TP1 + r0] = v;
    }
    __syncthreads();
    #pragma unroll
    for (int it = 0; it < 4; ++it) {
        int idx = tid + it*NTHR;
        int row = idx >> 5, dq = (idx & 31)*4;
        float se = sEg[row];
        float sw = sbeta[row] * se;
        float4 k4 = *(const float4*)&sK[row*KP1 + dq];
        k4.x*=sw; k4.y*=sw; k4.z*=sw; k4.w*=sw;
        *(float4*)&sXw[row*DK_ + dq] = k4;
        float4 q4 = *(const float4*)&sQ[row*KP1 + dq];
        q4.x*=se; q4.y*=se; q4.z*=se; q4.w*=se;
        *(float4*)&g_qg[cb + row*DK_ + dq] = q4;
    }
    #pragma unroll
    for (int it = 0; it < 4; ++it) {
        int idx = tid + it*NTHR;
        int d = idx >> 4, r0 = (idx & 15)*4;
        float4 kt = *(const float4*)&sKt[d*TP1 + r0];
        kt.x *= sdec[r0+0]; kt.y *= sdec[r0+1]; kt.z *= sdec[r0+2]; kt.w *= sdec[r0+3];
        *(float4*)&g_kdt[cb + d*CH_ + r0] = kt;
    }
    __syncthreads();

    // P4: stacked [K;Q] @ K^T via f32x2 dot products
    {
        const int jg = tid & 7, ig = tid >> 3;      // rows 2ig,2ig+1 of stack
        const float* ar0;
        const float* ar1;
        if (ig < 32) { ar0 = &sK[(2*ig)*KP1];    ar1 = &sK[(2*ig+1)*KP1]; }
        else         { ar0 = &sQ[(2*ig-64)*KP1]; ar1 = &sQ[(2*ig-63)*KP1]; }
        u64 acc[2][8];
        #pragma unroll
        for (int rr=0; rr<2; ++rr)
            #pragma unroll
            for (int m=0; m<8; ++m) acc[rr][m] = 0ull;
        #pragma unroll 4
        for (int d0 = 0; d0 < DK_; d0 += 4) {
            ulonglong2 a0 = *(const ulonglong2*)(ar0 + d0);
            ulonglong2 a1 = *(const ulonglong2*)(ar1 + d0);
            #pragma unroll
            for (int m = 0; m < 8; ++m) {
                ulonglong2 bv = *(const ulonglong2*)&sK[(jg + 8*m)*KP1 + d0];
                fma2(acc[0][m], a0.x, bv.x); fma2(acc[0][m], a0.y, bv.y);
                fma2(acc[1][m], a1.x, bv.x); fma2(acc[1][m], a1.y, bv.y);
            }
        }
        if (ig < 32) {
            #pragma unroll
            for (int rr=0; rr<2; ++rr) {
                int i = 2*ig + rr;
                float f = sbeta[i] * sEg[i];
                #pragma unroll
                for (int m=0; m<8; ++m) {
                    int j = jg + 8*m;
                    sA[i*AP1 + j] = (i > j) ? hsum2(acc[rr][m])*f*sEgi[j] : 0.f;
                }
            }
        } else {
            #pragma unroll
            for (int rr=0; rr<2; ++rr) {
                int i = 2*ig + rr - 64;
                float f = sEg[i];
                #pragma unroll
                for (int m=0; m<8; ++m) {
                    int j = jg + 8*m;
                    g_att[ab + i*CH_ + j] = (i >= j) ? hsum2(acc[rr][m])*f*sEgi[j] : 0.f;
                }
            }
        }
    }
    __syncthreads();

    // P5: invert 8x8 diagonal blocks
    if (warp < 8 && lane < 8) {
        const int blk = warp, R0 = blk*8, c = lane;
        float x[8];
        #pragma unroll
        for (int i = 0; i < 8; ++i) {
            float v = (i == c) ? 1.f : 0.f;
            #pragma unroll
            for (int l = 0; l < 8; ++l)
                if (l < i) v -= sA[(R0+i)*AP1 + (R0+l)] * x[l];
            x[i] = v;
        }
        #pragma unroll
        for (int i = 0; i < 8; ++i) sTinv[blk*64 + i*8 + c] = x[i];
    }
    __syncthreads();

    // P6: blocked forward substitution
    {
        const int i = tid >> 6;
        const int c0 = (tid & 63) * 4;
        float4 acc = {0.f,0.f,0.f,0.f};
        #pragma unroll
        for (int l = 0; l < 8; ++l) {
            float t = sTinv[0*64 + i*8 + l];
            float4 x = ldX(sXv, sXw, l, c0);
            acc.x += t*x.x; acc.y += t*x.y; acc.z += t*x.z; acc.w += t*x.w;
        }
        __syncthreads();
        stX(sXv, sXw, i, c0, acc);
        __syncthreads();
        for (int blk = 1; blk < 8; ++blk) {
            const int R0 = blk*8, row = R0 + i;
            float4 s = ldX(sXv, sXw, row, c0);
            #pragma unroll 4
            for (int m = 0; m < R0; ++m) {
                float a = sA[row*AP1 + m];
                float4 x = ldX(sXv, sXw, m, c0);
                s.x -= a*x.x; s.y -= a*x.y; s.z -= a*x.z; s.w -= a*x.w;
            }
            stX(sXv, sXw, row, c0, s);
            __syncthreads();
            float4 ac = {0.f,0.f,0.f,0.f};
            #pragma unroll
            for (int l = 0; l < 8; ++l) {
                float t = sTinv[blk*64 + i*8 + l];
                float4 x = ldX(sXv, sXw, R0 + l, c0);
                ac.x += t*x.x; ac.y += t*x.y; ac.z += t*x.z; ac.w += t*x.w;
            }
            __syncthreads();
            stX(sXv, sXw, row, c0, ac);
            __syncthreads();
        }
    }

    // P7: store u (slice-blocked) and kcd
    #pragma unroll
    for (int it = 0; it < 4; ++it) {
        int idx = tid + it*NTHR;
        int row = idx >> 5, c0 = (idx & 31)*4;
        float4 uv = *(const float4*)&sXv[row*DK_ + c0];
        int vsb = c0 >> 5, jj = c0 & 31;
        *(float4*)&g_u[cb + (size_t)vsb*(CH_*DVS) + row*DVS + jj] = uv;
        float4 wv = *(const float4*)&sXw[row*DK_ + c0];
        *(float4*)&g_w[cb + row*DK_ + c0] = wv;
    }
}

// ================================ KERNEL 2 ================================
// f32x2 dot-product scan: state stored transposed St[j][d]; v_new transposed.
#define SP 132   // sWQ / sSt pitch
#define VP 68    // sVnT / sKdt / sAttn pitch
#define SM2_FLOATS (128*SP + 32*SP + 32*VP + 128*VP + 64*VP)

__global__ __launch_bounds__(NTHR, 1)
void gdr_scan(float* __restrict__ gout)
{
    extern __shared__ float sm[];
    float* sWQ   = sm;                 // [128][132] rows 0-63 = kcd, 64-127 = qg
    float* sSt   = sWQ + 128*SP;       // [32][132]  state transposed [j][d]
    float* sVnT  = sSt + 32*SP;        // [32][68]   v_new transposed [j][r]
    float* sKdt  = sVnT + 32*VP;       // [128][68]  [d][r]
    float* sAttn = sKdt + 128*VP;      // [64][68]

    const int vs = blockIdx.x, h = blockIdx.y, b = blockIdx.z;
    const int tid = threadIdx.x;
    const int bh = b*H_ + h;
    const int jg = tid & 7, ig = tid >> 3;   // j in {jg+8m}, rows {2ig,2ig+1}

    for (int i = tid; i < 32*SP; i += NTHR) sSt[i] = 0.f;

    for (int n = 0; n < NCH; ++n) {
        const size_t cb = (size_t)(bh*NCH + n) * (CH_*DK_);
        const size_t ab = (size_t)(bh*NCH + n) * (CH_*CH_);
        const int s0 = n * CH_;

        // ---- stage ----
        #pragma unroll
        for (int it = 0; it < 4; ++it) {
            int idx = tid + it*NTHR;
            int row = idx >> 5, dq = (idx & 31)*4;
            *(float4*)&sWQ[row*SP + dq]      = *(const float4*)&g_w[cb + row*DK_ + dq];
            *(float4*)&sWQ[(64+row)*SP + dq] = *(const float4*)&g_qg[cb + row*DK_ + dq];
        }
        #pragma unroll
        for (int it = 0; it < 4; ++it) {
            int idx = tid + it*NTHR;
            int d = idx >> 4, r0 = (idx & 15)*4;
            *(float4*)&sKdt[d*VP + r0] = *(const float4*)&g_kdt[cb + d*CH_ + r0];
        }
        #pragma unroll
        for (int it = 0; it < 2; ++it) {
            int idx = tid + it*NTHR;
            int row = idx >> 4, c0 = (idx & 15)*4;
            *(float4*)&sAttn[row*VP + c0] = *(const float4*)&g_att[ab + row*CH_ + c0];
        }
        float ureg[2][4];
        if (tid < 256) {
            #pragma unroll
            for (int rr = 0; rr < 2; ++rr)
                #pragma unroll
                for (int m = 0; m < 4; ++m)
                    ureg[rr][m] = g_u[cb + (size_t)vs*(CH_*DVS) + (2*ig+rr)*DVS + jg + 8*m];
        }
        __syncthreads();

        // ---- phase A: [W;Qg](128x128) @ St^T -> v_new rows (tid<256) / o1 (tid>=256)
        u64 acc[2][4];
        #pragma unroll
        for (int rr=0; rr<2; ++rr)
            #pragma unroll
            for (int m=0; m<4; ++m) acc[rr][m] = 0ull;
        {
            const float* ar0 = &sWQ[(2*ig)*SP];
            const float* ar1 = &sWQ[(2*ig+1)*SP];
            #pragma unroll 4
            for (int d0 = 0; d0 < DK_; d0 += 4) {
                ulonglong2 a0 = *(const ulonglong2*)(ar0 + d0);
                ulonglong2 a1 = *(const ulonglong2*)(ar1 + d0);
                #pragma unroll
                for (int m = 0; m < 4; ++m) {
                    ulonglong2 bv = *(const ulonglong2*)&sSt[(jg + 8*m)*SP + d0];
                    fma2(acc[0][m], a0.x, bv.x); fma2(acc[0][m], a0.y, bv.y);
                    fma2(acc[1][m], a1.x, bv.x); fma2(acc[1][m], a1.y, bv.y);
                }
            }
        }
        float o1[2][4];
        if (tid < 256) {
            #pragma unroll
            for (int m = 0; m < 4; ++m) {
                float2 vn;
                vn.x = ureg[0][m] - hsum2(acc[0][m]);
                vn.y = ureg[1][m] - hsum2(acc[1][m]);
                *(float2*)&sVnT[(jg + 8*m)*VP + 2*ig] = vn;
            }
        } else {
            #pragma unroll
            for (int rr=0; rr<2; ++rr)
                #pragma unroll
                for (int m=0; m<4; ++m) o1[rr][m] = hsum2(acc[rr][m]);
        }
        __syncthreads();

        // ---- phase B ----
        if (tid < 256) {
            // state update: St[j][d] = St*eL + sum_r vnT[j][r]*Kdt[d][r]
            const int d0 = ig*4;            // ig = 0..31
            u64 acc2[4][4];
            #pragma unroll
            for (int m=0; m<4; ++m)
                #pragma unroll
                for (int dd=0; dd<4; ++dd) acc2[m][dd] = 0ull;
            #pragma unroll 2
            for (int r0 = 0; r0 < CH_; r0 += 4) {
                ulonglong2 kd[4], vv[4];
                #pragma unroll
                for (int dd=0; dd<4; ++dd)
                    kd[dd] = *(const ulonglong2*)&sKdt[(d0+dd)*VP + r0];
                #pragma unroll
                for (int m=0; m<4; ++m)
                    vv[m] = *(const ulonglong2*)&sVnT[(jg + 8*m)*VP + r0];
                #pragma unroll
                for (int m=0; m<4; ++m)
                    #pragma unroll
                    for (int dd=0; dd<4; ++dd) {
                        fma2(acc2[m][dd], vv[m].x, kd[dd].x);
                        fma2(acc2[m][dd], vv[m].y, kd[dd].y);
                    }
            }
            const float eL = g_eL[bh*NCH + n];
            #pragma unroll
            for (int m = 0; m < 4; ++m) {
                float4 st = *(const float4*)&sSt[(jg + 8*m)*SP + d0];
                st.x = st.x*eL + hsum2(acc2[m][0]);
                st.y = st.y*eL + hsum2(acc2[m][1]);
                st.z = st.z*eL + hsum2(acc2[m][2]);
                st.w = st.w*eL + hsum2(acc2[m][3]);
                *(float4*)&sSt[(jg + 8*m)*SP + d0] = st;
            }
        } else {
            // o2 = attn @ v_new; out = o1 + o2
            const int rg2 = ig - 32;        // 0..31, rows 2rg2,2rg2+1
            u64 acc3[2][4];
            #pragma unroll
            for (int rr=0; rr<2; ++rr)
                #pragma unroll
                for (int m=0; m<4; ++m) acc3[rr][m] = 0ull;
            const float* ar0 = &sAttn[(2*rg2)*VP];
            const float* ar1 = &sAttn[(2*rg2+1)*VP];
            #pragma unroll 4
            for (int c0 = 0; c0 < CH_; c0 += 4) {
                ulonglong2 a0 = *(const ulonglong2*)(ar0 + c0);
                ulonglong2 a1 = *(const ulonglong2*)(ar1 + c0);
                #pragma unroll
                for (int m = 0; m < 4; ++m) {
                    ulonglong2 bv = *(const ulonglong2*)&sVnT[(jg + 8*m)*VP + c0];
                    fma2(acc3[0][m], a0.x, bv.x); fma2(acc3[0][m], a0.y, bv.y);
                    fma2(acc3[1][m], a1.x, bv.x); fma2(acc3[1][m], a1.y, bv.y);
                }
            }
            #pragma unroll
            for (int rr = 0; rr < 2; ++rr) {
                int row = 2*rg2 + rr;
                float* op = gout + ((size_t)((b*S_ + s0 + row)*H_ + h))*DV_ + vs*DVS;
                #pragma unroll
                for (int m = 0; m < 4; ++m)
                    op[jg + 8*m] = o1[rr][m] + hsum2(acc3[rr][m]);
            }
        }
        __syncthreads();
    }
}

extern "C" void kernel_launch(void* const* d_in, const int* in_sizes, int n_in,
                              void* d_out, int out_size) {
    (void)in_sizes; (void)n_in; (void)out_size;
    const float* q    = (const float*)d_in[0];
    const float* k    = (const float*)d_in[1];
    const float* v    = (const float*)d_in[2];
    const float* g    = (const float*)d_in[3];
    const float* beta = (const float*)d_in[4];
    float* out = (float*)d_out;

    size_t smem1 = (size_t)SM1_FLOATS * sizeof(float);
    size_t smem2 = (size_t)SM2_FLOATS * sizeof(float);
    cudaFuncSetAttribute(gdr_prep, cudaFuncAttributeMaxDynamicSharedMemorySize, (int)smem1);
    cudaFuncSetAttribute(gdr_scan, cudaFuncAttributeMaxDynamicSharedMemorySize, (int)smem2);

    dim3 grid1(NCH, H_, B_);
    gdr_prep<<<grid1, NTHR, smem1>>>(q, k, v, g, beta);

    dim3 grid2(NSPLIT, H_, B_);
    gdr_scan<<<grid2, NTHR, smem2>>>(out);
}